// round 14
// baseline (speedup 1.0000x reference)
#include <cuda_runtime.h>
#include <cuda_fp16.h>
#include <cstdint>

// ============================ problem constants =============================
#define BATCH 8192
#define INF   4096
#define OUTF  4096

// ============================ scratch (static, no runtime alloc) ============
__device__ __align__(16) __half g_B[(size_t)OUTF * INF];   // quantized weight (exact small ints)
__device__ __align__(16) __half g_X[(size_t)BATCH * INF];  // fp16 x
__device__ float g_scale[OUTF];                            // row_norm/60

// ============================ PTX helpers ==================================
__device__ __forceinline__ uint32_t smem_u32(const void* p) {
    uint32_t a;
    asm("{ .reg .u64 t; cvta.to.shared.u64 t, %1; cvt.u32.u64 %0, t; }" : "=r"(a) : "l"(p));
    return a;
}

__device__ __forceinline__ void cp16(uint32_t dst, const void* src) {
    asm volatile("cp.async.cg.shared.global [%0], [%1], 16;" :: "r"(dst), "l"(src) : "memory");
}

__device__ __forceinline__ void ldsm4(uint32_t* r, uint32_t addr) {
    asm volatile("ldmatrix.sync.aligned.m8n8.x4.shared.b16 {%0,%1,%2,%3}, [%4];"
                 : "=r"(r[0]), "=r"(r[1]), "=r"(r[2]), "=r"(r[3]) : "r"(addr));
}

__device__ __forceinline__ void mma16816(float* d, const uint32_t* a, uint32_t b0, uint32_t b1) {
    asm volatile(
        "mma.sync.aligned.m16n8k16.row.col.f32.f16.f16.f32 "
        "{%0,%1,%2,%3}, {%4,%5,%6,%7}, {%8,%9}, {%0,%1,%2,%3};"
        : "+f"(d[0]), "+f"(d[1]), "+f"(d[2]), "+f"(d[3])
        : "r"(a[0]), "r"(a[1]), "r"(a[2]), "r"(a[3]), "r"(b0), "r"(b1));
}

// Full XOR swizzle for 128B rows (8x 16B chunks): chunk ^= row&7.
// Conflict-free for 8-row ldmatrix wavefronts and cp.async wavefronts.
__device__ __forceinline__ uint32_t swz128(int r, int c) {
    return (uint32_t)(r * 128 + ((c ^ (r & 7)) << 4));
}

// ============================ fused prep kernel ============================
// Blocks [0, 2048): weight quantization, 2 rows/block, 4 warps/row, row held
//   in registers (single DRAM pass). Norm: fp32 squares grouped by 4 -> fp64
//   warp shfl reduce -> fp64 4-way smem combine.
//   q = clip(rint(w/norm*60), -8, 7) stored as fp16 (exact small ints).
// Blocks [2048, ...): x fp32 -> fp16 conversion, 4 float4 per thread.
constexpr int WBLK = OUTF / 2;   // 2048 weight blocks

__global__ __launch_bounds__(256) void prep_kernel(const float* __restrict__ W,
                                                   const float* __restrict__ X) {
    __shared__ double s_part[2][4];
    __shared__ float  s_norm[2];

    if (blockIdx.x < WBLK) {
        const int wid  = threadIdx.x >> 5;   // 0..7
        const int lane = threadIdx.x & 31;
        const int rowi = wid >> 2;           // 0..1 (row within block)
        const int wq   = wid & 3;            // quarter of the row
        const int r = blockIdx.x * 2 + rowi;
        const float4* row = (const float4*)(W + (size_t)r * INF);

        float4 v[8];
        double ss = 0.0;
#pragma unroll
        for (int i = 0; i < 8; i++) {
            v[i] = row[wq * 256 + i * 32 + lane];
            float s = v[i].x * v[i].x + v[i].y * v[i].y + v[i].z * v[i].z + v[i].w * v[i].w;
            ss += (double)s;
        }
#pragma unroll
        for (int off = 16; off; off >>= 1)
            ss += __shfl_xor_sync(0xffffffffu, ss, off);
        if (lane == 0) s_part[rowi][wq] = ss;
        __syncthreads();
        if (threadIdx.x < 2) {
            double t = s_part[threadIdx.x][0] + s_part[threadIdx.x][1]
                     + s_part[threadIdx.x][2] + s_part[threadIdx.x][3];
            float n = fmaxf((float)sqrt(t), 1e-8f);
            s_norm[threadIdx.x] = n;
            g_scale[blockIdx.x * 2 + threadIdx.x] = __fdiv_rn(n, 60.0f);
        }
        __syncthreads();
        const float n_safe = s_norm[rowi];

        __half* outp = g_B + (size_t)r * INF;
#pragma unroll
        for (int i = 0; i < 8; i++) {
            const float w4[4] = { v[i].x, v[i].y, v[i].z, v[i].w };
            float q[4];
#pragma unroll
            for (int e = 0; e < 4; e++) {
                float ws = __fmul_rn(__fdiv_rn(w4[e], n_safe), 60.0f);  // IEEE, jnp op order
                float qq = rintf(ws);                                   // round-half-even
                q[e] = fminf(fmaxf(qq, -8.0f), 7.0f);
            }
            __half2* p = (__half2*)(outp + (size_t)(wq * 256 + i * 32 + lane) * 4);
            p[0] = __floats2half2_rn(q[0], q[1]);
            p[1] = __floats2half2_rn(q[2], q[3]);
        }
    } else {
        // 4 float4 per thread for memory-level parallelism
        const size_t base = (size_t)(blockIdx.x - WBLK) * 1024 + threadIdx.x;
        float4 v[4];
#pragma unroll
        for (int j = 0; j < 4; j++) v[j] = ((const float4*)X)[base + j * 256];
#pragma unroll
        for (int j = 0; j < 4; j++) {
            __half2* p = (__half2*)g_X + 2 * (base + j * 256);
            p[0] = __floats2half2_rn(v[j].x, v[j].y);
            p[1] = __floats2half2_rn(v[j].z, v[j].w);
        }
    }
}

// ============================ GEMM kernel ==================================
// CTA tile 256(M) x 128(N), BK=64, 8 warps of 64x64 (4Mx2N), 3-stage
// cp.async pipeline (144KB). Region-scoped synchronization: the producer is
// remapped so each smem region is written ONLY by the warps that read it
// (A-region warp_m: 2 warps; B-region warp_n: 4 warps). The CTA-wide
// __syncthreads becomes wait_group 0 + bar.sync(1+warp_m, 64) +
// bar.sync(5+warp_n, 128): barrier skew couples 2-4 warps instead of 8.
constexpr int STAGES      = 3;
constexpr int KT          = INF / 64;        // 64 k-iters
constexpr int A_BYTES     = 256 * 128;       // 32 KB per stage
constexpr int B_BYTES     = 128 * 128;       // 16 KB per stage
constexpr int STAGE_BYTES = A_BYTES + B_BYTES;
constexpr int SMEM_TOTAL  = STAGES * STAGE_BYTES;   // 144 KB

__global__ __launch_bounds__(256, 1)
void gemm_kernel(const float* __restrict__ bias, float* __restrict__ out) {
    extern __shared__ char smem[];
    const uint32_t sb = smem_u32(smem);
    const int tid = threadIdx.x;
    const int wid = tid >> 5, lane = tid & 31;

    const int warp_m = wid & 3;         // 4 warps along M (64 rows each)
    const int warp_n = wid >> 2;        // 2 warps along N (64 cols each)

    // tile raster: GROUP_M = 8 for L2 reuse (full B panel = 32MB fits L2)
    const int pid = blockIdx.x;
    const int GW = 8 * 32;
    const int grp = pid / GW, rem = pid % GW;
    const int m0 = (grp * 8 + (rem & 7)) * 256;
    const int n0 = (rem >> 3) * 128;

    // ---- region-mapped producer: each warp fills what it will read ----
    // A region warp_m (64 rows): warps {warp_m, warp_m+4}; 1 row/thread, 8 cp16.
    // B region warp_n (64 rows): warps {4*warp_n+0..3}; half row/thread, 4 cp16.
    const int row_a = warp_m * 64 + warp_n * 32 + lane;       // CTA-local A row
    const int tb    = warp_m * 32 + lane;                     // 0..127 within n-group
    const int row_b = warp_n * 64 + (tb >> 1);
    const int cb0   = (tb & 1) * 4;                           // chunk base in B row
    const char* pAr = (const char*)(g_X + (size_t)(m0 + row_a) * INF);
    const char* pBr = (const char*)(g_B + (size_t)(n0 + row_b) * INF) + cb0 * 16;
    const uint32_t dA = (uint32_t)(row_a * 128);
    const uint32_t xA = (uint32_t)(row_a & 7);
    const uint32_t dB = A_BYTES + (uint32_t)(row_b * 128);
    const uint32_t xB = (uint32_t)(row_b & 7);

    int pst = 0;                                              // produce stage rotator
    auto produce = [&]() {
        const uint32_t base = sb + (uint32_t)pst * STAGE_BYTES;
#pragma unroll
        for (int c = 0; c < 8; c++)
            cp16(base + dA + (((uint32_t)c ^ xA) << 4), pAr + c * 16);
#pragma unroll
        for (int j = 0; j < 4; j++)
            cp16(base + dB + (((uint32_t)(cb0 + j) ^ xB) << 4), pBr + j * 16);
        asm volatile("cp.async.commit_group;" ::: "memory");
        pAr += 128; pBr += 128;
        pst = (pst == STAGES - 1) ? 0 : pst + 1;
    };

    produce();  // stage 0
    produce();  // stage 1

    // ---- per-lane fragment addressing ----
    const int lr = lane & 15, lc = lane >> 4;

    // folded address: addr = stage_base + (offx ^ (ch16<<4)), ch16 = 2*ch+lc
    uint32_t aoffx[4], boffx[4];
#pragma unroll
    for (int mi = 0; mi < 4; mi++) {
        int rA = warp_m * 64 + mi * 16 + lr;
        aoffx[mi] = (uint32_t)(rA * 128) | (uint32_t)((rA & 7) << 4);
    }
#pragma unroll
    for (int nj2 = 0; nj2 < 4; nj2++) {
        int rB = warp_n * 64 + nj2 * 16 + lr;
        boffx[nj2] = (uint32_t)(rB * 128) | (uint32_t)((rB & 7) << 4);
    }

    float acc[4][8][4];
#pragma unroll
    for (int mi = 0; mi < 4; mi++)
#pragma unroll
        for (int nj = 0; nj < 8; nj++)
#pragma unroll
            for (int e = 0; e < 4; e++) acc[mi][nj][e] = 0.0f;

    // ---- prologue: drain stages 0+1, region barriers, preload stage-0 ch0 ----
    asm volatile("cp.async.wait_group 0;" ::: "memory");
    asm volatile("bar.sync %0, 64;"  :: "r"(1 + warp_m) : "memory");
    asm volatile("bar.sync %0, 128;" :: "r"(5 + warp_n) : "memory");

    uint32_t a[4][4];        // A frags, reloaded in place per ch
    uint32_t b[2][4][4];     // B frags, double buffered [buf][nj2]
    {
        const uint32_t cx0 = (uint32_t)(lc << 4);
#pragma unroll
        for (int nj2 = 0; nj2 < 4; nj2++)
            ldsm4(b[0][nj2], sb + A_BYTES + (boffx[nj2] ^ cx0));
#pragma unroll
        for (int mi = 0; mi < 4; mi++)
            ldsm4(a[mi], sb + (aoffx[mi] ^ cx0));
    }

    // ---- mainloop: 64 iters; ch0 frags of stage k already in registers ----
    int st = 0;
#pragma unroll 1
    for (int k = 0; k < KT; ++k) {
        if (k) {
            // own cp.async groups (incl. slot k+1) drained, then region
            // barriers: writers == readers per region, so release implies
            // stage k AND k+1 data complete + visible for this warp's regions.
            asm volatile("cp.async.wait_group 0;" ::: "memory");
            asm volatile("bar.sync %0, 64;"  :: "r"(1 + warp_m) : "memory");
            asm volatile("bar.sync %0, 128;" :: "r"(5 + warp_n) : "memory");
        }
        if (k + 2 < KT) produce();                    // fills slot (k+2)%3

        const int stn = (st == STAGES - 1) ? 0 : st + 1;
        const uint32_t base   = sb + (uint32_t)st  * STAGE_BYTES;
        const uint32_t bbase  = base + A_BYTES;
        const uint32_t nbase  = sb + (uint32_t)stn * STAGE_BYTES;
        const uint32_t nbbase = nbase + A_BYTES;
        const bool pf = (k + 1 < KT);
        const uint32_t cx0 = (uint32_t)(lc << 4);

#pragma unroll
        for (int ch = 0; ch < 4; ch++) {
            const int cur = ch & 1, nxt = cur ^ 1;
            const uint32_t cxn = (uint32_t)((2 * (ch + 1) + lc) << 4);
            if (ch < 3) {            // prefetch next-ch B (same stage)
#pragma unroll
                for (int nj2 = 0; nj2 < 4; nj2++)
                    ldsm4(b[nxt][nj2], bbase + (boffx[nj2] ^ cxn));
            } else if (pf) {         // prefetch NEXT STAGE ch0 B (nxt==0)
#pragma unroll
                for (int nj2 = 0; nj2 < 4; nj2++)
                    ldsm4(b[nxt][nj2], nbbase + (boffx[nj2] ^ cx0));
            }
#pragma unroll
            for (int mi = 0; mi < 4; mi++) {
#pragma unroll
                for (int nj = 0; nj < 8; nj++)
                    mma16816(acc[mi][nj], a[mi], b[cur][nj >> 1][nj & 1], b[cur][nj >> 1][(nj & 1) + 2]);
                if (ch < 3)          // a[mi] dead: reload same stage ch+1
                    ldsm4(a[mi], base + (aoffx[mi] ^ cxn));
                else if (pf)         // or NEXT STAGE ch0 (crosses barrier in regs)
                    ldsm4(a[mi], nbase + (aoffx[mi] ^ cx0));
            }
        }
        st = stn;
    }

    // ---- epilogue: scale[n]*acc + bias[n], direct coalesced float2 stores ----
    const int ncol = n0 + warp_n * 64 + (lane & 3) * 2;
    float2 sc[8], bi[8];
#pragma unroll
    for (int nj = 0; nj < 8; nj++) {
        sc[nj] = make_float2(__ldg(g_scale + ncol + nj * 8), __ldg(g_scale + ncol + nj * 8 + 1));
        bi[nj] = make_float2(__ldg(bias + ncol + nj * 8), __ldg(bias + ncol + nj * 8 + 1));
    }
    const int rbase = m0 + warp_m * 64 + (lane >> 2);
#pragma unroll
    for (int mi = 0; mi < 4; mi++) {
#pragma unroll
        for (int h = 0; h < 2; h++) {
            float* po = out + (size_t)(rbase + mi * 16 + h * 8) * OUTF + ncol;
#pragma unroll
            for (int nj = 0; nj < 8; nj++) {
                float2 v;
                v.x = fmaf(acc[mi][nj][2 * h + 0], sc[nj].x, bi[nj].x);
                v.y = fmaf(acc[mi][nj][2 * h + 1], sc[nj].y, bi[nj].y);
                *(float2*)(po + nj * 8) = v;
            }
        }
    }
}

// ============================ launch =======================================
extern "C" void kernel_launch(void* const* d_in, const int* in_sizes, int n_in,
                              void* d_out, int out_size) {
    const float* x = (const float*)d_in[0];
    const float* w = (const float*)d_in[1];
    const float* bias = (const float*)d_in[2];
    float* out = (float*)d_out;

    cudaFuncSetAttribute(gemm_kernel, cudaFuncAttributeMaxDynamicSharedMemorySize, SMEM_TOTAL);

    const unsigned xblocks = (unsigned)((size_t)BATCH * INF / 16 / 256);  // 4 float4/thread
    prep_kernel<<<WBLK + xblocks, 256>>>(w, x);
    gemm_kernel<<<(BATCH / 256) * (OUTF / 128), 256, SMEM_TOTAL>>>(bias, out);
}

// round 15
// speedup vs baseline: 1.7094x; 1.7094x over previous
#include <cuda_runtime.h>
#include <cuda_fp16.h>
#include <cstdint>

// ============================ problem constants =============================
#define BATCH 8192
#define INF   4096
#define OUTF  4096

// ============================ scratch (static, no runtime alloc) ============
__device__ __align__(16) __half g_B[(size_t)OUTF * INF];   // quantized weight (exact small ints)
__device__ __align__(16) __half g_X[(size_t)BATCH * INF];  // fp16 x
__device__ float g_scale[OUTF];                            // row_norm/60

// ============================ PTX helpers ==================================
__device__ __forceinline__ uint32_t smem_u32(const void* p) {
    uint32_t a;
    asm("{ .reg .u64 t; cvta.to.shared.u64 t, %1; cvt.u32.u64 %0, t; }" : "=r"(a) : "l"(p));
    return a;
}

__device__ __forceinline__ void cp16(uint32_t dst, const void* src) {
    asm volatile("cp.async.cg.shared.global [%0], [%1], 16;" :: "r"(dst), "l"(src) : "memory");
}

__device__ __forceinline__ void ldsm4(uint32_t* r, uint32_t addr) {
    asm volatile("ldmatrix.sync.aligned.m8n8.x4.shared.b16 {%0,%1,%2,%3}, [%4];"
                 : "=r"(r[0]), "=r"(r[1]), "=r"(r[2]), "=r"(r[3]) : "r"(addr));
}

__device__ __forceinline__ void mma16816(float* d, const uint32_t* a, uint32_t b0, uint32_t b1) {
    asm volatile(
        "mma.sync.aligned.m16n8k16.row.col.f32.f16.f16.f32 "
        "{%0,%1,%2,%3}, {%4,%5,%6,%7}, {%8,%9}, {%0,%1,%2,%3};"
        : "+f"(d[0]), "+f"(d[1]), "+f"(d[2]), "+f"(d[3])
        : "r"(a[0]), "r"(a[1]), "r"(a[2]), "r"(a[3]), "r"(b0), "r"(b1));
}

// Full XOR swizzle for 128B rows (8x 16B chunks): chunk ^= row&7.
// Conflict-free for 8-row ldmatrix wavefronts and 8-lane cp.async wavefronts.
__device__ __forceinline__ uint32_t swz128(int r, int c) {
    return (uint32_t)(r * 128 + ((c ^ (r & 7)) << 4));
}

// ============================ fused prep kernel ============================
// Blocks [0, 2048): weight quantization, 2 rows/block, 4 warps/row, row held
//   in registers (single DRAM pass). Norm: fp32 squares grouped by 4 -> fp64
//   warp shfl reduce -> fp64 4-way smem combine.
//   q = clip(rint(w/norm*60), -8, 7) stored as fp16 (exact small ints).
// Blocks [2048, ...): x fp32 -> fp16 conversion, 4 float4 per thread.
constexpr int WBLK = OUTF / 2;   // 2048 weight blocks

__global__ __launch_bounds__(256) void prep_kernel(const float* __restrict__ W,
                                                   const float* __restrict__ X) {
    __shared__ double s_part[2][4];
    __shared__ float  s_norm[2];

    if (blockIdx.x < WBLK) {
        const int wid  = threadIdx.x >> 5;   // 0..7
        const int lane = threadIdx.x & 31;
        const int rowi = wid >> 2;           // 0..1 (row within block)
        const int wq   = wid & 3;            // quarter of the row
        const int r = blockIdx.x * 2 + rowi;
        const float4* row = (const float4*)(W + (size_t)r * INF);

        float4 v[8];
        double ss = 0.0;
#pragma unroll
        for (int i = 0; i < 8; i++) {
            v[i] = row[wq * 256 + i * 32 + lane];
            float s = v[i].x * v[i].x + v[i].y * v[i].y + v[i].z * v[i].z + v[i].w * v[i].w;
            ss += (double)s;
        }
#pragma unroll
        for (int off = 16; off; off >>= 1)
            ss += __shfl_xor_sync(0xffffffffu, ss, off);
        if (lane == 0) s_part[rowi][wq] = ss;
        __syncthreads();
        if (threadIdx.x < 2) {
            double t = s_part[threadIdx.x][0] + s_part[threadIdx.x][1]
                     + s_part[threadIdx.x][2] + s_part[threadIdx.x][3];
            float n = fmaxf((float)sqrt(t), 1e-8f);
            s_norm[threadIdx.x] = n;
            g_scale[blockIdx.x * 2 + threadIdx.x] = __fdiv_rn(n, 60.0f);
        }
        __syncthreads();
        const float n_safe = s_norm[rowi];

        __half* outp = g_B + (size_t)r * INF;
#pragma unroll
        for (int i = 0; i < 8; i++) {
            const float w4[4] = { v[i].x, v[i].y, v[i].z, v[i].w };
            float q[4];
#pragma unroll
            for (int e = 0; e < 4; e++) {
                float ws = __fmul_rn(__fdiv_rn(w4[e], n_safe), 60.0f);  // IEEE, jnp op order
                float qq = rintf(ws);                                   // round-half-even
                q[e] = fminf(fmaxf(qq, -8.0f), 7.0f);
            }
            __half2* p = (__half2*)(outp + (size_t)(wq * 256 + i * 32 + lane) * 4);
            p[0] = __floats2half2_rn(q[0], q[1]);
            p[1] = __floats2half2_rn(q[2], q[3]);
        }
    } else {
        // 4 float4 per thread for memory-level parallelism
        const size_t base = (size_t)(blockIdx.x - WBLK) * 1024 + threadIdx.x;
        float4 v[4];
#pragma unroll
        for (int j = 0; j < 4; j++) v[j] = ((const float4*)X)[base + j * 256];
#pragma unroll
        for (int j = 0; j < 4; j++) {
            __half2* p = (__half2*)g_X + 2 * (base + j * 256);
            p[0] = __floats2half2_rn(v[j].x, v[j].y);
            p[1] = __floats2half2_rn(v[j].z, v[j].w);
        }
    }
}

// ============================ GEMM kernel ==================================
// CTA tile 256(M) x 128(N), BK=64, 8 warps of 64x64 (4Mx2N), 4-stage
// cp.async pipeline (192KB) with wait_group 1: each group gets 2 full iters
// to land (DRAM/L2 latency tails no longer stall the barrier). Producer is
// the proven coalesced layout (8 threads/row). Cross-barrier register
// prefetch of next stage's ch0 fragments keeps the tensor pipe fed.
constexpr int STAGES      = 4;
constexpr int KT          = INF / 64;        // 64 k-iters
constexpr int A_BYTES     = 256 * 128;       // 32 KB per stage
constexpr int B_BYTES     = 128 * 128;       // 16 KB per stage
constexpr int STAGE_BYTES = A_BYTES + B_BYTES;
constexpr int SMEM_TOTAL  = STAGES * STAGE_BYTES;   // 192 KB

__global__ __launch_bounds__(256, 1)
void gemm_kernel(const float* __restrict__ bias, float* __restrict__ out) {
    extern __shared__ char smem[];
    const uint32_t sb = smem_u32(smem);
    const int tid = threadIdx.x;
    const int wid = tid >> 5, lane = tid & 31;

    // tile raster: GROUP_M = 8 for L2 reuse (full B panel = 32MB fits L2)
    const int pid = blockIdx.x;
    const int GW = 8 * 32;
    const int grp = pid / GW, rem = pid % GW;
    const int m0 = (grp * 8 + (rem & 7)) * 256;
    const int n0 = (rem >> 3) * 128;

    // ---- producer addressing: 256 threads, 12 cp16 each per BK=64 stage ----
    const int rowt = tid >> 3;          // 0..31
    const int c8   = tid & 7;           // 16B chunk within 128B row
    const char* pA = (const char*)(g_X + (size_t)(m0 + rowt) * INF) + c8 * 16;
    const char* pB = (const char*)(g_B + (size_t)(n0 + rowt) * INF) + c8 * 16;
    const uint32_t dA0 = swz128(rowt, c8);           // row&7 invariant under +32
    const uint32_t dB0 = A_BYTES + dA0;

    int pst = 0;                                      // produce stage rotator
    auto produce = [&]() {
        const uint32_t base = sb + (uint32_t)pst * STAGE_BYTES;
#pragma unroll
        for (int i = 0; i < 8; i++)
            cp16(base + dA0 + (uint32_t)i * (32 * 128), pA + (size_t)i * 32 * (INF * 2));
#pragma unroll
        for (int i = 0; i < 4; i++)
            cp16(base + dB0 + (uint32_t)i * (32 * 128), pB + (size_t)i * 32 * (INF * 2));
        asm volatile("cp.async.commit_group;" ::: "memory");
        pA += 128; pB += 128;
        pst = (pst + 1) & (STAGES - 1);
    };

    produce();  // slot 0 (group 0)
    produce();  // slot 1 (group 1)
    produce();  // slot 2 (group 2)

    // ---- per-lane fragment addressing ----
    const int warp_m = wid & 3;         // 4 warps along M (64 rows each)
    const int warp_n = wid >> 2;        // 2 warps along N (64 cols each)
    const int lr = lane & 15, lc = lane >> 4;

    // folded address: addr = stage_base + (offx ^ (ch16<<4)), ch16 = 2*ch+lc
    uint32_t aoffx[4], boffx[4];
#pragma unroll
    for (int mi = 0; mi < 4; mi++) {
        int rA = warp_m * 64 + mi * 16 + lr;
        aoffx[mi] = (uint32_t)(rA * 128) | (uint32_t)((rA & 7) << 4);
    }
#pragma unroll
    for (int nj2 = 0; nj2 < 4; nj2++) {
        int rB = warp_n * 64 + nj2 * 16 + lr;
        boffx[nj2] = (uint32_t)(rB * 128) | (uint32_t)((rB & 7) << 4);
    }

    float acc[4][8][4];
#pragma unroll
    for (int mi = 0; mi < 4; mi++)
#pragma unroll
        for (int nj = 0; nj < 8; nj++)
#pragma unroll
            for (int e = 0; e < 4; e++) acc[mi][nj][e] = 0.0f;

    // ---- prologue: groups 0,1 complete (slots 0,1); preload stage-0 ch0 ----
    asm volatile("cp.async.wait_group 1;" ::: "memory");
    __syncthreads();

    uint32_t a[4][4];        // A frags, reloaded in place per ch
    uint32_t b[2][4][4];     // B frags, double buffered [buf][nj2]
    {
        const uint32_t cx0 = (uint32_t)(lc << 4);
#pragma unroll
        for (int nj2 = 0; nj2 < 4; nj2++)
            ldsm4(b[0][nj2], sb + A_BYTES + (boffx[nj2] ^ cx0));
#pragma unroll
        for (int mi = 0; mi < 4; mi++)
            ldsm4(a[mi], sb + (aoffx[mi] ^ cx0));
    }

    // ---- mainloop: 64 iters; ch0 frags of stage k already in registers ----
    // Invariant at iter-k top after wait_group 1 + barrier: commits so far =
    // 3 + (k-1); all but newest complete => groups <= k+1 done = slots k
    // (consume) and k+1 (tail prefetch). Empty tail commits keep alignment.
    int st = 0;
#pragma unroll 1
    for (int k = 0; k < KT; ++k) {
        if (k) {
            asm volatile("cp.async.wait_group 1;" ::: "memory");
            __syncthreads();
        }
        if (k + 3 < KT) produce();                    // fills slot (k+3)&3
        else asm volatile("cp.async.commit_group;" ::: "memory");

        const int stn = (st + 1) & (STAGES - 1);
        const uint32_t base   = sb + (uint32_t)st  * STAGE_BYTES;
        const uint32_t bbase  = base + A_BYTES;
        const uint32_t nbase  = sb + (uint32_t)stn * STAGE_BYTES;
        const uint32_t nbbase = nbase + A_BYTES;
        const bool pf = (k + 1 < KT);
        const uint32_t cx0 = (uint32_t)(lc << 4);

#pragma unroll
        for (int ch = 0; ch < 4; ch++) {
            const int cur = ch & 1, nxt = cur ^ 1;
            const uint32_t cxn = (uint32_t)((2 * (ch + 1) + lc) << 4);
            if (ch < 3) {            // prefetch next-ch B (same stage)
#pragma unroll
                for (int nj2 = 0; nj2 < 4; nj2++)
                    ldsm4(b[nxt][nj2], bbase + (boffx[nj2] ^ cxn));
            } else if (pf) {         // prefetch NEXT STAGE ch0 B (nxt==0)
#pragma unroll
                for (int nj2 = 0; nj2 < 4; nj2++)
                    ldsm4(b[nxt][nj2], nbbase + (boffx[nj2] ^ cx0));
            }
#pragma unroll
            for (int mi = 0; mi < 4; mi++) {
#pragma unroll
                for (int nj = 0; nj < 8; nj++)
                    mma16816(acc[mi][nj], a[mi], b[cur][nj >> 1][nj & 1], b[cur][nj >> 1][(nj & 1) + 2]);
                if (ch < 3)          // a[mi] dead: reload same stage ch+1
                    ldsm4(a[mi], base + (aoffx[mi] ^ cxn));
                else if (pf)         // or NEXT STAGE ch0 (crosses barrier in regs)
                    ldsm4(a[mi], nbase + (aoffx[mi] ^ cx0));
            }
        }
        st = stn;
    }

    // ---- epilogue: scale[n]*acc + bias[n], direct coalesced float2 stores ----
    const int ncol = n0 + warp_n * 64 + (lane & 3) * 2;
    float2 sc[8], bi[8];
#pragma unroll
    for (int nj = 0; nj < 8; nj++) {
        sc[nj] = make_float2(__ldg(g_scale + ncol + nj * 8), __ldg(g_scale + ncol + nj * 8 + 1));
        bi[nj] = make_float2(__ldg(bias + ncol + nj * 8), __ldg(bias + ncol + nj * 8 + 1));
    }
    const int rbase = m0 + warp_m * 64 + (lane >> 2);
#pragma unroll
    for (int mi = 0; mi < 4; mi++) {
#pragma unroll
        for (int h = 0; h < 2; h++) {
            float* po = out + (size_t)(rbase + mi * 16 + h * 8) * OUTF + ncol;
#pragma unroll
            for (int nj = 0; nj < 8; nj++) {
                float2 v;
                v.x = fmaf(acc[mi][nj][2 * h + 0], sc[nj].x, bi[nj].x);
                v.y = fmaf(acc[mi][nj][2 * h + 1], sc[nj].y, bi[nj].y);
                *(float2*)(po + nj * 8) = v;
            }
        }
    }
}

// ============================ launch =======================================
extern "C" void kernel_launch(void* const* d_in, const int* in_sizes, int n_in,
                              void* d_out, int out_size) {
    const float* x = (const float*)d_in[0];
    const float* w = (const float*)d_in[1];
    const float* bias = (const float*)d_in[2];
    float* out = (float*)d_out;

    cudaFuncSetAttribute(gemm_kernel, cudaFuncAttributeMaxDynamicSharedMemorySize, SMEM_TOTAL);

    const unsigned xblocks = (unsigned)((size_t)BATCH * INF / 16 / 256);  // 4 float4/thread
    prep_kernel<<<WBLK + xblocks, 256>>>(w, x);
    gemm_kernel<<<(BATCH / 256) * (OUTF / 128), 256, SMEM_TOTAL>>>(bias, out);
}

// round 16
// speedup vs baseline: 1.7123x; 1.0017x over previous
#include <cuda_runtime.h>
#include <cuda_fp16.h>
#include <cstdint>

// ============================ problem constants =============================
#define BATCH 8192
#define INF   4096
#define OUTF  4096

// ============================ scratch (static, no runtime alloc) ============
__device__ __align__(16) __half g_B[(size_t)OUTF * INF];   // quantized weight (exact small ints)
__device__ __align__(16) __half g_X[(size_t)BATCH * INF];  // fp16 x
__device__ float g_scale[OUTF];                            // row_norm/60

// ============================ PTX helpers ==================================
__device__ __forceinline__ uint32_t smem_u32(const void* p) {
    uint32_t a;
    asm("{ .reg .u64 t; cvta.to.shared.u64 t, %1; cvt.u32.u64 %0, t; }" : "=r"(a) : "l"(p));
    return a;
}

__device__ __forceinline__ void cp16(uint32_t dst, const void* src) {
    asm volatile("cp.async.cg.shared.global [%0], [%1], 16;" :: "r"(dst), "l"(src) : "memory");
}

__device__ __forceinline__ void ldsm4(uint32_t* r, uint32_t addr) {
    asm volatile("ldmatrix.sync.aligned.m8n8.x4.shared.b16 {%0,%1,%2,%3}, [%4];"
                 : "=r"(r[0]), "=r"(r[1]), "=r"(r[2]), "=r"(r[3]) : "r"(addr));
}

__device__ __forceinline__ void mma16816(float* d, const uint32_t* a, uint32_t b0, uint32_t b1) {
    asm volatile(
        "mma.sync.aligned.m16n8k16.row.col.f32.f16.f16.f32 "
        "{%0,%1,%2,%3}, {%4,%5,%6,%7}, {%8,%9}, {%0,%1,%2,%3};"
        : "+f"(d[0]), "+f"(d[1]), "+f"(d[2]), "+f"(d[3])
        : "r"(a[0]), "r"(a[1]), "r"(a[2]), "r"(a[3]), "r"(b0), "r"(b1));
}

// Full XOR swizzle for 128B rows (8x 16B chunks): chunk ^= row&7.
// Conflict-free for 8-row ldmatrix wavefronts and 8-lane cp.async wavefronts.
__device__ __forceinline__ uint32_t swz128(int r, int c) {
    return (uint32_t)(r * 128 + ((c ^ (r & 7)) << 4));
}

// pack 4 floats -> 4 halfs in one uint2 (two __half2)
__device__ __forceinline__ uint2 pack4h(float a, float b, float c, float d) {
    __half2 lo = __floats2half2_rn(a, b);
    __half2 hi = __floats2half2_rn(c, d);
    uint2 r;
    r.x = *(uint32_t*)&lo;
    r.y = *(uint32_t*)&hi;
    return r;
}

// ============================ fused prep kernel ============================
// Blocks [0, 2048): weight quantization, 2 rows/block, 4 warps/row, row held
//   in registers (single DRAM pass). Norm: fp32 squares grouped by 4 -> fp64
//   warp shfl reduce -> fp64 4-way smem combine. Quantize via one reciprocal
//   per row (ws = w * (60/n)); 8-byte packed stores.
// Blocks [2048, ...): x fp32 -> fp16 conversion, 4 float4/thread, 8B stores.
constexpr int WBLK = OUTF / 2;   // 2048 weight blocks

__global__ __launch_bounds__(256) void prep_kernel(const float* __restrict__ W,
                                                   const float* __restrict__ X) {
    __shared__ double s_part[2][4];
    __shared__ float  s_r60[2];

    if (blockIdx.x < WBLK) {
        const int wid  = threadIdx.x >> 5;   // 0..7
        const int lane = threadIdx.x & 31;
        const int rowi = wid >> 2;           // 0..1 (row within block)
        const int wq   = wid & 3;            // quarter of the row
        const int r = blockIdx.x * 2 + rowi;
        const float4* row = (const float4*)(W + (size_t)r * INF);

        float4 v[8];
        double ss = 0.0;
#pragma unroll
        for (int i = 0; i < 8; i++) {
            v[i] = row[wq * 256 + i * 32 + lane];
            float s = v[i].x * v[i].x + v[i].y * v[i].y + v[i].z * v[i].z + v[i].w * v[i].w;
            ss += (double)s;
        }
#pragma unroll
        for (int off = 16; off; off >>= 1)
            ss += __shfl_xor_sync(0xffffffffu, ss, off);
        if (lane == 0) s_part[rowi][wq] = ss;
        __syncthreads();
        if (threadIdx.x < 2) {
            double t = s_part[threadIdx.x][0] + s_part[threadIdx.x][1]
                     + s_part[threadIdx.x][2] + s_part[threadIdx.x][3];
            float n = fmaxf((float)sqrt(t), 1e-8f);
            s_r60[threadIdx.x] = __fdiv_rn(60.0f, n);
            g_scale[blockIdx.x * 2 + threadIdx.x] = __fdiv_rn(n, 60.0f);
        }
        __syncthreads();
        const float r60 = s_r60[rowi];

        __half* outp = g_B + (size_t)r * INF;
#pragma unroll
        for (int i = 0; i < 8; i++) {
            const float w4[4] = { v[i].x, v[i].y, v[i].z, v[i].w };
            float q[4];
#pragma unroll
            for (int e = 0; e < 4; e++) {
                float ws = __fmul_rn(w4[e], r60);   // one-recip path (<=2ulp vs (w/n)*60)
                float qq = rintf(ws);               // round-half-even like jnp.round
                q[e] = fminf(fmaxf(qq, -8.0f), 7.0f);
            }
            *(uint2*)(outp + (size_t)(wq * 256 + i * 32 + lane) * 4) =
                pack4h(q[0], q[1], q[2], q[3]);
        }
    } else {
        // 4 float4 per thread for memory-level parallelism; 8B packed stores
        const size_t base = (size_t)(blockIdx.x - WBLK) * 1024 + threadIdx.x;
        float4 v[4];
#pragma unroll
        for (int j = 0; j < 4; j++) v[j] = ((const float4*)X)[base + j * 256];
#pragma unroll
        for (int j = 0; j < 4; j++) {
            *((uint2*)g_X + (base + j * 256)) = pack4h(v[j].x, v[j].y, v[j].z, v[j].w);
        }
    }
}

// ============================ GEMM kernel ==================================
// (FROZEN — R15 best: 625us, tensor 72.3%)
// CTA tile 256(M) x 128(N), BK=64, 8 warps of 64x64 (4Mx2N), 4-stage
// cp.async pipeline (192KB) with wait_group 1. Coalesced producer
// (8 threads/row). Cross-barrier register prefetch of next stage's ch0.
constexpr int STAGES      = 4;
constexpr int KT          = INF / 64;        // 64 k-iters
constexpr int A_BYTES     = 256 * 128;       // 32 KB per stage
constexpr int B_BYTES     = 128 * 128;       // 16 KB per stage
constexpr int STAGE_BYTES = A_BYTES + B_BYTES;
constexpr int SMEM_TOTAL  = STAGES * STAGE_BYTES;   // 192 KB

__global__ __launch_bounds__(256, 1)
void gemm_kernel(const float* __restrict__ bias, float* __restrict__ out) {
    extern __shared__ char smem[];
    const uint32_t sb = smem_u32(smem);
    const int tid = threadIdx.x;
    const int wid = tid >> 5, lane = tid & 31;

    // tile raster: GROUP_M = 8 for L2 reuse (full B panel = 32MB fits L2)
    const int pid = blockIdx.x;
    const int GW = 8 * 32;
    const int grp = pid / GW, rem = pid % GW;
    const int m0 = (grp * 8 + (rem & 7)) * 256;
    const int n0 = (rem >> 3) * 128;

    // ---- producer addressing: 256 threads, 12 cp16 each per BK=64 stage ----
    const int rowt = tid >> 3;          // 0..31
    const int c8   = tid & 7;           // 16B chunk within 128B row
    const char* pA = (const char*)(g_X + (size_t)(m0 + rowt) * INF) + c8 * 16;
    const char* pB = (const char*)(g_B + (size_t)(n0 + rowt) * INF) + c8 * 16;
    const uint32_t dA0 = swz128(rowt, c8);           // row&7 invariant under +32
    const uint32_t dB0 = A_BYTES + dA0;

    int pst = 0;                                      // produce stage rotator
    auto produce = [&]() {
        const uint32_t base = sb + (uint32_t)pst * STAGE_BYTES;
#pragma unroll
        for (int i = 0; i < 8; i++)
            cp16(base + dA0 + (uint32_t)i * (32 * 128), pA + (size_t)i * 32 * (INF * 2));
#pragma unroll
        for (int i = 0; i < 4; i++)
            cp16(base + dB0 + (uint32_t)i * (32 * 128), pB + (size_t)i * 32 * (INF * 2));
        asm volatile("cp.async.commit_group;" ::: "memory");
        pA += 128; pB += 128;
        pst = (pst + 1) & (STAGES - 1);
    };

    produce();  // slot 0 (group 0)
    produce();  // slot 1 (group 1)
    produce();  // slot 2 (group 2)

    // ---- per-lane fragment addressing ----
    const int warp_m = wid & 3;         // 4 warps along M (64 rows each)
    const int warp_n = wid >> 2;        // 2 warps along N (64 cols each)
    const int lr = lane & 15, lc = lane >> 4;

    // folded address: addr = stage_base + (offx ^ (ch16<<4)), ch16 = 2*ch+lc
    uint32_t aoffx[4], boffx[4];
#pragma unroll
    for (int mi = 0; mi < 4; mi++) {
        int rA = warp_m * 64 + mi * 16 + lr;
        aoffx[mi] = (uint32_t)(rA * 128) | (uint32_t)((rA & 7) << 4);
    }
#pragma unroll
    for (int nj2 = 0; nj2 < 4; nj2++) {
        int rB = warp_n * 64 + nj2 * 16 + lr;
        boffx[nj2] = (uint32_t)(rB * 128) | (uint32_t)((rB & 7) << 4);
    }

    float acc[4][8][4];
#pragma unroll
    for (int mi = 0; mi < 4; mi++)
#pragma unroll
        for (int nj = 0; nj < 8; nj++)
#pragma unroll
            for (int e = 0; e < 4; e++) acc[mi][nj][e] = 0.0f;

    // ---- prologue: groups 0,1 complete (slots 0,1); preload stage-0 ch0 ----
    asm volatile("cp.async.wait_group 1;" ::: "memory");
    __syncthreads();

    uint32_t a[4][4];        // A frags, reloaded in place per ch
    uint32_t b[2][4][4];     // B frags, double buffered [buf][nj2]
    {
        const uint32_t cx0 = (uint32_t)(lc << 4);
#pragma unroll
        for (int nj2 = 0; nj2 < 4; nj2++)
            ldsm4(b[0][nj2], sb + A_BYTES + (boffx[nj2] ^ cx0));
#pragma unroll
        for (int mi = 0; mi < 4; mi++)
            ldsm4(a[mi], sb + (aoffx[mi] ^ cx0));
    }

    // ---- mainloop: 64 iters; ch0 frags of stage k already in registers ----
    // Invariant at iter-k top after wait_group 1 + barrier: commits so far =
    // 3 + (k-1); all but newest complete => groups <= k+1 done = slots k
    // (consume) and k+1 (tail prefetch). Empty tail commits keep alignment.
    int st = 0;
#pragma unroll 1
    for (int k = 0; k < KT; ++k) {
        if (k) {
            asm volatile("cp.async.wait_group 1;" ::: "memory");
            __syncthreads();
        }
        if (k + 3 < KT) produce();                    // fills slot (k+3)&3
        else asm volatile("cp.async.commit_group;" ::: "memory");

        const int stn = (st + 1) & (STAGES - 1);
        const uint32_t base   = sb + (uint32_t)st  * STAGE_BYTES;
        const uint32_t bbase  = base + A_BYTES;
        const uint32_t nbase  = sb + (uint32_t)stn * STAGE_BYTES;
        const uint32_t nbbase = nbase + A_BYTES;
        const bool pf = (k + 1 < KT);
        const uint32_t cx0 = (uint32_t)(lc << 4);

#pragma unroll
        for (int ch = 0; ch < 4; ch++) {
            const int cur = ch & 1, nxt = cur ^ 1;
            const uint32_t cxn = (uint32_t)((2 * (ch + 1) + lc) << 4);
            if (ch < 3) {            // prefetch next-ch B (same stage)
#pragma unroll
                for (int nj2 = 0; nj2 < 4; nj2++)
                    ldsm4(b[nxt][nj2], bbase + (boffx[nj2] ^ cxn));
            } else if (pf) {         // prefetch NEXT STAGE ch0 B (nxt==0)
#pragma unroll
                for (int nj2 = 0; nj2 < 4; nj2++)
                    ldsm4(b[nxt][nj2], nbbase + (boffx[nj2] ^ cx0));
            }
#pragma unroll
            for (int mi = 0; mi < 4; mi++) {
#pragma unroll
                for (int nj = 0; nj < 8; nj++)
                    mma16816(acc[mi][nj], a[mi], b[cur][nj >> 1][nj & 1], b[cur][nj >> 1][(nj & 1) + 2]);
                if (ch < 3)          // a[mi] dead: reload same stage ch+1
                    ldsm4(a[mi], base + (aoffx[mi] ^ cxn));
                else if (pf)         // or NEXT STAGE ch0 (crosses barrier in regs)
                    ldsm4(a[mi], nbase + (aoffx[mi] ^ cx0));
            }
        }
        st = stn;
    }

    // ---- epilogue: scale[n]*acc + bias[n], direct coalesced float2 stores ----
    const int ncol = n0 + warp_n * 64 + (lane & 3) * 2;
    float2 sc[8], bi[8];
#pragma unroll
    for (int nj = 0; nj < 8; nj++) {
        sc[nj] = make_float2(__ldg(g_scale + ncol + nj * 8), __ldg(g_scale + ncol + nj * 8 + 1));
        bi[nj] = make_float2(__ldg(bias + ncol + nj * 8), __ldg(bias + ncol + nj * 8 + 1));
    }
    const int rbase = m0 + warp_m * 64 + (lane >> 2);
#pragma unroll
    for (int mi = 0; mi < 4; mi++) {
#pragma unroll
        for (int h = 0; h < 2; h++) {
            float* po = out + (size_t)(rbase + mi * 16 + h * 8) * OUTF + ncol;
#pragma unroll
            for (int nj = 0; nj < 8; nj++) {
                float2 v;
                v.x = fmaf(acc[mi][nj][2 * h + 0], sc[nj].x, bi[nj].x);
                v.y = fmaf(acc[mi][nj][2 * h + 1], sc[nj].y, bi[nj].y);
                *(float2*)(po + nj * 8) = v;
            }
        }
    }
}

// ============================ launch =======================================
extern "C" void kernel_launch(void* const* d_in, const int* in_sizes, int n_in,
                              void* d_out, int out_size) {
    const float* x = (const float*)d_in[0];
    const float* w = (const float*)d_in[1];
    const float* bias = (const float*)d_in[2];
    float* out = (float*)d_out;

    cudaFuncSetAttribute(gemm_kernel, cudaFuncAttributeMaxDynamicSharedMemorySize, SMEM_TOTAL);

    const unsigned xblocks = (unsigned)((size_t)BATCH * INF / 16 / 256);  // 4 float4/thread
    prep_kernel<<<WBLK + xblocks, 256>>>(w, x);
    gemm_kernel<<<(BATCH / 256) * (OUTF / 128), 256, SMEM_TOTAL>>>(bias, out);
}